// round 1
// baseline (speedup 1.0000x reference)
#include <cuda_runtime.h>
#include <cuda_bf16.h>
#include <math.h>

// Problem constants
#define BATCH 2
#define SEQ   2048
#define NH    32
#define HD    128
#define HID   4096           // NH*HD
#define QKVN  12288          // 3*HID
#define MTOK  (BATCH*SEQ)    // 4096 tokens

// ---------------- scratch (device globals: no allocation allowed) -------------
__device__ float g_qkv[(size_t)MTOK * QKVN];   // raw qkv projection (201 MB)
__device__ float g_q[(size_t)MTOK * HID];      // roped q (67 MB)
__device__ float g_k[(size_t)MTOK * HID];      // roped k (67 MB)
__device__ float g_ctx[(size_t)MTOK * HID];    // attention context (67 MB)
__device__ int   g_mask[MTOK];                 // vision expert mask

// ---------------- mask ----------------
__global__ void mask_kernel(const int* __restrict__ tt, int* __restrict__ mask) {
    int idx = blockIdx.x * blockDim.x + threadIdx.x;
    if (idx >= MTOK) return;
    int s = idx & (SEQ - 1);
    int v = (s + 1 < SEQ) && (tt[idx] == 1) && (tt[idx + 1] == 1);
    mask[idx] = v;
}

// ---------------- fp32 SGEMM with per-row expert-predicated store ----------------
// C[m][n] = sum_k A[m][k] * B[k][n], stored only where mask[m]==expert.
// BM=BN=128, BK=16, 256 threads, 8x8 per thread.
__global__ __launch_bounds__(256)
void sgemm_expert(const float* __restrict__ A, const float* __restrict__ B,
                  float* __restrict__ C, int N, int K,
                  const int* __restrict__ mask, int expert) {
    __shared__ float As[16][128];
    __shared__ float Bs[16][128];

    const int tid = threadIdx.x;
    const int tx = tid & 15;          // 0..15 -> output cols tx*8..
    const int ty = tid >> 4;          // 0..15 -> output rows ty*8..
    const int m0 = blockIdx.y * 128;
    const int n0 = blockIdx.x * 128;

    float acc[8][8];
#pragma unroll
    for (int i = 0; i < 8; i++)
#pragma unroll
        for (int j = 0; j < 8; j++) acc[i][j] = 0.f;

    float ar[8], br[8];

    for (int k0 = 0; k0 < K; k0 += 16) {
        // A tile: 128 rows x 16 cols -> 512 float4, 2 per thread, store transposed
#pragma unroll
        for (int i = 0; i < 2; i++) {
            int f = tid + i * 256;
            int r = f >> 2;
            int c4 = (f & 3) << 2;
            float4 v = *(const float4*)&A[(size_t)(m0 + r) * K + k0 + c4];
            As[c4 + 0][r] = v.x;
            As[c4 + 1][r] = v.y;
            As[c4 + 2][r] = v.z;
            As[c4 + 3][r] = v.w;
        }
        // B tile: 16 rows x 128 cols -> 512 float4, natural layout
#pragma unroll
        for (int i = 0; i < 2; i++) {
            int f = tid + i * 256;
            int r = f >> 5;
            int c4 = (f & 31) << 2;
            *(float4*)&Bs[r][c4] = *(const float4*)&B[(size_t)(k0 + r) * N + n0 + c4];
        }
        __syncthreads();

#pragma unroll
        for (int kk = 0; kk < 16; kk++) {
#pragma unroll
            for (int i = 0; i < 8; i++) ar[i] = As[kk][ty * 8 + i];
#pragma unroll
            for (int j = 0; j < 8; j++) br[j] = Bs[kk][tx * 8 + j];
#pragma unroll
            for (int i = 0; i < 8; i++)
#pragma unroll
                for (int j = 0; j < 8; j++) acc[i][j] += ar[i] * br[j];
        }
        __syncthreads();
    }

#pragma unroll
    for (int i = 0; i < 8; i++) {
        int m = m0 + ty * 8 + i;
        if (mask[m] != expert) continue;
        float* cp = &C[(size_t)m * N + n0 + tx * 8];
        *(float4*)(cp + 0) = make_float4(acc[i][0], acc[i][1], acc[i][2], acc[i][3]);
        *(float4*)(cp + 4) = make_float4(acc[i][4], acc[i][5], acc[i][6], acc[i][7]);
    }
}

// ---------------- RoPE: split qkv, rotate q/k into g_q/g_k ----------------
__global__ void rope_kernel(const float* __restrict__ qkv, const int* __restrict__ pos_ids,
                            float* __restrict__ q, float* __restrict__ k) {
    int idx = blockIdx.x * blockDim.x + threadIdx.x;   // MTOK*NH*64
    if (idx >= MTOK * NH * 64) return;
    int i = idx & 63;
    int h = (idx >> 6) & 31;
    int m = idx >> 11;

    float pos = (float)pos_ids[m];
    // inv_freq = 10000^(-i/64)
    float freq = expf(-(float)i * (9.210340371976184f / 64.f));
    float ang = pos * freq;
    float c = cosf(ang);
    float s = sinf(ang);

    const float* qs = qkv + (size_t)m * QKVN + h * HD;
    const float* ks = qs + HID;
    float q0 = qs[i], q1 = qs[i + 64];
    float k0 = ks[i], k1 = ks[i + 64];

    size_t o = (size_t)m * HID + h * HD;
    q[o + i]      = q0 * c - q1 * s;
    q[o + i + 64] = q1 * c + q0 * s;
    k[o + i]      = k0 * c - k1 * s;
    k[o + i + 64] = k1 * c + k0 * s;
}

// ---------------- causal flash attention (fp32, warp per query row) ----------------
// grid: (SEQ/8, NH, BATCH), block 256 (8 warps -> 8 query rows)
__global__ __launch_bounds__(256)
void attn_kernel(const float* __restrict__ Q, const float* __restrict__ Kg,
                 const float* __restrict__ qkv, float* __restrict__ ctx) {
    const int b = blockIdx.z;
    const int h = blockIdx.y;
    const int warp = threadIdx.x >> 5;
    const int lane = threadIdx.x & 31;
    const int qrow = blockIdx.x * 8 + warp;

    __shared__ float Ks[32][129];   // padded for conflict-free per-lane row reads
    __shared__ float Vs[32][128];
    __shared__ float Qs[8][128];

    // load 8 q rows
    {
        int f = threadIdx.x;
        int r = f >> 5;
        int c4 = (f & 31) << 2;
        *(float4*)&Qs[r][c4] =
            *(const float4*)&Q[((size_t)(b * SEQ + blockIdx.x * 8 + r)) * HID + h * HD + c4];
    }

    float o0 = 0.f, o1 = 0.f, o2 = 0.f, o3 = 0.f;
    float mrun = -INFINITY, lsum = 0.f;
    const float scale = 0.088388347648318447f;  // 1/sqrt(128)
    const int qmax = blockIdx.x * 8 + 7;
    const int ntiles = qmax / 32 + 1;

    for (int t = 0; t < ntiles; t++) {
        __syncthreads();
        // load K,V tile (32 rows x 128)
#pragma unroll
        for (int i = 0; i < 4; i++) {
            int f = threadIdx.x + i * 256;
            int r = f >> 5;
            int c4 = (f & 31) << 2;
            size_t row = (size_t)(b * SEQ + t * 32 + r);
            float4 kv = *(const float4*)&Kg[row * HID + h * HD + c4];
            Ks[r][c4 + 0] = kv.x; Ks[r][c4 + 1] = kv.y;
            Ks[r][c4 + 2] = kv.z; Ks[r][c4 + 3] = kv.w;
            *(float4*)&Vs[r][c4] =
                *(const float4*)&qkv[row * QKVN + 2 * HID + h * HD + c4];
        }
        __syncthreads();

        // one score per lane
        int kcol = t * 32 + lane;
        float s = 0.f;
        const float* qp = Qs[warp];
#pragma unroll 8
        for (int d = 0; d < 128; d++) s += qp[d] * Ks[lane][d];
        s *= scale;
        if (kcol > qrow) s = -INFINITY;

        // online softmax
        float mt = s;
#pragma unroll
        for (int off = 16; off; off >>= 1) mt = fmaxf(mt, __shfl_xor_sync(0xffffffffu, mt, off));
        float mnew = fmaxf(mrun, mt);
        float corr = expf(mrun - mnew);           // 0 on first tile (mrun=-inf, mnew finite)
        float p = expf(s - mnew);
        float psum = p;
#pragma unroll
        for (int off = 16; off; off >>= 1) psum += __shfl_xor_sync(0xffffffffu, psum, off);
        lsum = lsum * corr + psum;
        o0 *= corr; o1 *= corr; o2 *= corr; o3 *= corr;

#pragma unroll
        for (int j = 0; j < 32; j++) {
            float pj = __shfl_sync(0xffffffffu, p, j);
            float4 v = *(const float4*)&Vs[j][lane * 4];
            o0 += pj * v.x; o1 += pj * v.y; o2 += pj * v.z; o3 += pj * v.w;
        }
        mrun = mnew;
    }

    float inv = 1.f / lsum;
    *(float4*)&ctx[((size_t)(b * SEQ + qrow)) * HID + h * HD + lane * 4] =
        make_float4(o0 * inv, o1 * inv, o2 * inv, o3 * inv);
}

// ---------------- launch ----------------
extern "C" void kernel_launch(void* const* d_in, const int* in_sizes, int n_in,
                              void* d_out, int out_size) {
    const float* hidden = (const float*)d_in[0];
    const int*   tt     = (const int*)d_in[1];
    const int*   pos    = (const int*)d_in[2];
    const float* wvq    = (const float*)d_in[3];
    const float* wlq    = (const float*)d_in[4];
    const float* wvd    = (const float*)d_in[5];
    const float* wld    = (const float*)d_in[6];
    float* out = (float*)d_out;

    float *qkv_p, *q_p, *k_p, *ctx_p;
    int* mask_p;
    cudaGetSymbolAddress((void**)&qkv_p, g_qkv);
    cudaGetSymbolAddress((void**)&q_p, g_q);
    cudaGetSymbolAddress((void**)&k_p, g_k);
    cudaGetSymbolAddress((void**)&ctx_p, g_ctx);
    cudaGetSymbolAddress((void**)&mask_p, g_mask);

    mask_kernel<<<MTOK / 256, 256>>>(tt, mask_p);

    // QKV projection: both experts, predicated store
    {
        dim3 grid(QKVN / 128, MTOK / 128);
        sgemm_expert<<<grid, 256>>>(hidden, wvq, qkv_p, QKVN, HID, mask_p, 1);
        sgemm_expert<<<grid, 256>>>(hidden, wlq, qkv_p, QKVN, HID, mask_p, 0);
    }

    // RoPE
    {
        int total = MTOK * NH * 64;
        rope_kernel<<<total / 256, 256>>>(qkv_p, pos, q_p, k_p);
    }

    // Attention
    {
        dim3 grid(SEQ / 8, NH, BATCH);
        attn_kernel<<<grid, 256>>>(q_p, k_p, qkv_p, ctx_p);
    }

    // Dense projection: both experts, predicated store into d_out
    {
        dim3 grid(HID / 128, MTOK / 128);
        sgemm_expert<<<grid, 256>>>(ctx_p, wvd, out, HID, HID, mask_p, 1);
        sgemm_expert<<<grid, 256>>>(ctx_p, wld, out, HID, HID, mask_p, 0);
    }
}

// round 3
// speedup vs baseline: 2.3663x; 2.3663x over previous
#include <cuda_runtime.h>
#include <cuda_bf16.h>
#include <math.h>
#include <stdint.h>

// Problem constants
#define BATCH 2
#define SEQ   2048
#define NH    32
#define HD    128
#define HID   4096           // NH*HD
#define QKVN  12288          // 3*HID
#define MTOK  (BATCH*SEQ)    // 4096 tokens

// GEMM tile config (mma.sync m16n8k8 tf32)
#define BM 128
#define BN 128
#define BK 32
#define STAGES 3
#define AS_STRIDE 36          // floats per A-row (bank-conflict-free fragment reads)
#define BS_STRIDE 136         // floats per B-row
#define AS_BYTES (BM * AS_STRIDE * 4)               // 18432
#define BS_BYTES (BK * BS_STRIDE * 4)               // 17408
#define STAGE_BYTES (AS_BYTES + BS_BYTES)           // 35840
#define GEMM_SMEM (STAGES * STAGE_BYTES)            // 107520

// ---------------- scratch (device globals: no allocation allowed) -------------
__device__ float g_qkv[(size_t)MTOK * QKVN];
__device__ float g_q[(size_t)MTOK * HID];
__device__ float g_k[(size_t)MTOK * HID];
__device__ float g_ctx[(size_t)MTOK * HID];
__device__ int   g_mask[MTOK];

// ---------------- helpers ----------------
__device__ __forceinline__ uint32_t smem_u32(const void* p) {
    uint32_t a;
    asm("{ .reg .u64 t; cvta.to.shared.u64 t, %1; cvt.u32.u64 %0, t; }" : "=r"(a) : "l"(p));
    return a;
}
__device__ __forceinline__ void cp16(uint32_t dst, const void* src) {
    asm volatile("cp.async.cg.shared.global [%0], [%1], 16;" :: "r"(dst), "l"(src));
}
__device__ __forceinline__ void cp_commit() {
    asm volatile("cp.async.commit_group;" ::: "memory");
}
template <int N>
__device__ __forceinline__ void cp_wait() {
    asm volatile("cp.async.wait_group %0;" :: "n"(N) : "memory");
}
__device__ __forceinline__ uint32_t f2tf32(float f) {
    uint32_t r;
    asm("cvt.rna.tf32.f32 %0, %1;" : "=r"(r) : "f"(f));
    return r;
}
__device__ __forceinline__ void mma_tf32(float* c, uint32_t a0, uint32_t a1, uint32_t a2, uint32_t a3,
                                         uint32_t b0, uint32_t b1) {
    asm volatile(
        "mma.sync.aligned.m16n8k8.row.col.f32.tf32.tf32.f32 "
        "{%0,%1,%2,%3}, {%4,%5,%6,%7}, {%8,%9}, {%0,%1,%2,%3};"
        : "+f"(c[0]), "+f"(c[1]), "+f"(c[2]), "+f"(c[3])
        : "r"(a0), "r"(a1), "r"(a2), "r"(a3), "r"(b0), "r"(b1));
}

// ---------------- mask ----------------
__global__ void mask_kernel(const int* __restrict__ tt, int* __restrict__ mask) {
    int idx = blockIdx.x * blockDim.x + threadIdx.x;
    if (idx >= MTOK) return;
    int s = idx & (SEQ - 1);
    int v = (s + 1 < SEQ) && (tt[idx] == 1) && (tt[idx + 1] == 1);
    mask[idx] = v;
}

// ---------------- tensor-core tf32 GEMM ----------------
// C[m][n] = sum_k A[m][k] * W[k][n]; store rows where mask[m]==expert.
// A: [M][HID] row-major. W: [HID][N] row-major (read as Bs[k][n] directly).
// Block tile 128x128, K-chunk 32, 3-stage cp.async pipeline.
// 8 warps in 2(M) x 4(N); warp tile 64x32 = 4x4 m16n8 mma tiles.
__global__ __launch_bounds__(256)
void gemm_tc(const float* __restrict__ A, const float* __restrict__ W,
             float* __restrict__ C, int N, const int* __restrict__ mask, int expert) {
    extern __shared__ char smem[];
    const uint32_t sb = smem_u32(smem);
    const int tid = threadIdx.x;
    const int wid = tid >> 5;
    const int lane = tid & 31;
    const int lm = lane >> 2;     // group id (0..7)
    const int lq = lane & 3;      // thread-in-group (0..3)
    const int warp_m = wid & 1;   // 0..1
    const int warp_n = wid >> 1;  // 0..3
    const int m0 = blockIdx.x * BM;
    const int n0 = blockIdx.y * BN;

    const float* Ag = A + (size_t)m0 * HID;
    const float* Wg = W + n0;

    // per-thread load slots
    // A: 1024 float4 (128 rows x 8 slots); thread does 4
    const int ar_[1] = {0};
    // precompute load indices
    int a_r[4], a_c[4], b_r[4], b_c[4];
#pragma unroll
    for (int i = 0; i < 4; i++) {
        int idx = tid + i * 256;
        a_r[i] = idx >> 3; a_c[i] = idx & 7;       // row 0..127, slot 0..7
        b_r[i] = idx >> 5; b_c[i] = idx & 31;      // krow 0..31, slot 0..31
    }
    (void)ar_;

    auto load_stage = [&](int stage, int chunk) {
        uint32_t as = sb + stage * STAGE_BYTES;
        uint32_t bs = as + AS_BYTES;
        const float* Asrc = Ag + chunk * BK;
        const float* Bsrc = Wg + (size_t)chunk * BK * N;
#pragma unroll
        for (int i = 0; i < 4; i++)
            cp16(as + a_r[i] * (AS_STRIDE * 4) + a_c[i] * 16,
                 Asrc + (size_t)a_r[i] * HID + a_c[i] * 4);
#pragma unroll
        for (int i = 0; i < 4; i++)
            cp16(bs + b_r[i] * (BS_STRIDE * 4) + b_c[i] * 16,
                 Bsrc + (size_t)b_r[i] * N + b_c[i] * 4);
    };

    float c[4][4][4];
#pragma unroll
    for (int mt = 0; mt < 4; mt++)
#pragma unroll
        for (int nt = 0; nt < 4; nt++)
#pragma unroll
            for (int j = 0; j < 4; j++) c[mt][nt][j] = 0.f;

    const int NC = HID / BK;  // 128 chunks

    load_stage(0, 0); cp_commit();
    load_stage(1, 1); cp_commit();

    for (int ch = 0; ch < NC; ch++) {
        cp_wait<1>();
        __syncthreads();

        if (ch + 2 < NC) load_stage((ch + 2) % STAGES, ch + 2);
        cp_commit();

        const float* As = (const float*)(smem + (ch % STAGES) * STAGE_BYTES);
        const float* Bs = (const float*)(smem + (ch % STAGES) * STAGE_BYTES + AS_BYTES);

#pragma unroll
        for (int kk = 0; kk < BK; kk += 8) {
            uint32_t af[4][4], bf[4][2];
#pragma unroll
            for (int mt = 0; mt < 4; mt++) {
                int r = warp_m * 64 + mt * 16 + lm;
                const float* ap = As + r * AS_STRIDE + kk + lq;
                af[mt][0] = f2tf32(ap[0]);
                af[mt][1] = f2tf32(ap[8 * AS_STRIDE]);
                af[mt][2] = f2tf32(ap[4]);
                af[mt][3] = f2tf32(ap[8 * AS_STRIDE + 4]);
            }
#pragma unroll
            for (int nt = 0; nt < 4; nt++) {
                int col = warp_n * 32 + nt * 8 + lm;
                const float* bp = Bs + (kk + lq) * BS_STRIDE + col;
                bf[nt][0] = f2tf32(bp[0]);
                bf[nt][1] = f2tf32(bp[4 * BS_STRIDE]);
            }
#pragma unroll
            for (int mt = 0; mt < 4; mt++)
#pragma unroll
                for (int nt = 0; nt < 4; nt++)
                    mma_tf32(c[mt][nt], af[mt][0], af[mt][1], af[mt][2], af[mt][3],
                             bf[nt][0], bf[nt][1]);
        }
        __syncthreads();
    }

    // epilogue: predicated store
#pragma unroll
    for (int mt = 0; mt < 4; mt++) {
        int r0 = m0 + warp_m * 64 + mt * 16 + lm;
        int r1 = r0 + 8;
        bool on0 = (mask[r0] == expert);
        bool on1 = (mask[r1] == expert);
        float* p0 = C + (size_t)r0 * N + n0 + warp_n * 32;
        float* p1 = C + (size_t)r1 * N + n0 + warp_n * 32;
#pragma unroll
        for (int nt = 0; nt < 4; nt++) {
            int col = nt * 8 + 2 * lq;
            if (on0) *(float2*)(p0 + col) = make_float2(c[mt][nt][0], c[mt][nt][1]);
            if (on1) *(float2*)(p1 + col) = make_float2(c[mt][nt][2], c[mt][nt][3]);
        }
    }
}

// ---------------- RoPE ----------------
__global__ void rope_kernel(const float* __restrict__ qkv, const int* __restrict__ pos_ids,
                            float* __restrict__ q, float* __restrict__ k) {
    int idx = blockIdx.x * blockDim.x + threadIdx.x;   // MTOK*NH*64
    if (idx >= MTOK * NH * 64) return;
    int i = idx & 63;
    int h = (idx >> 6) & 31;
    int m = idx >> 11;

    float pos = (float)pos_ids[m];
    float freq = expf(-(float)i * (9.210340371976184f / 64.f));
    float ang = pos * freq;
    float cv = cosf(ang);
    float sv = sinf(ang);

    const float* qs = qkv + (size_t)m * QKVN + h * HD;
    const float* ks = qs + HID;
    float q0 = qs[i], q1 = qs[i + 64];
    float k0 = ks[i], k1 = ks[i + 64];

    size_t o = (size_t)m * HID + h * HD;
    q[o + i]      = q0 * cv - q1 * sv;
    q[o + i + 64] = q1 * cv + q0 * sv;
    k[o + i]      = k0 * cv - k1 * sv;
    k[o + i + 64] = k1 * cv + k0 * sv;
}

// ---------------- causal flash attention (fp32, warp per query row) ----------------
__global__ __launch_bounds__(256)
void attn_kernel(const float* __restrict__ Q, const float* __restrict__ Kg,
                 const float* __restrict__ qkv, float* __restrict__ ctx) {
    const int b = blockIdx.z;
    const int h = blockIdx.y;
    const int warp = threadIdx.x >> 5;
    const int lane = threadIdx.x & 31;
    const int qrow = blockIdx.x * 8 + warp;

    __shared__ float Ks[32][129];
    __shared__ float Vs[32][128];
    __shared__ float Qs[8][128];

    {
        int f = threadIdx.x;
        int r = f >> 5;
        int c4 = (f & 31) << 2;
        *(float4*)&Qs[r][c4] =
            *(const float4*)&Q[((size_t)(b * SEQ + blockIdx.x * 8 + r)) * HID + h * HD + c4];
    }

    float o0 = 0.f, o1 = 0.f, o2 = 0.f, o3 = 0.f;
    float mrun = -INFINITY, lsum = 0.f;
    const float scale = 0.088388347648318447f;
    const int qmax = blockIdx.x * 8 + 7;
    const int ntiles = qmax / 32 + 1;

    for (int t = 0; t < ntiles; t++) {
        __syncthreads();
#pragma unroll
        for (int i = 0; i < 4; i++) {
            int f = threadIdx.x + i * 256;
            int r = f >> 5;
            int c4 = (f & 31) << 2;
            size_t row = (size_t)(b * SEQ + t * 32 + r);
            float4 kv = *(const float4*)&Kg[row * HID + h * HD + c4];
            Ks[r][c4 + 0] = kv.x; Ks[r][c4 + 1] = kv.y;
            Ks[r][c4 + 2] = kv.z; Ks[r][c4 + 3] = kv.w;
            *(float4*)&Vs[r][c4] =
                *(const float4*)&qkv[row * QKVN + 2 * HID + h * HD + c4];
        }
        __syncthreads();

        int kcol = t * 32 + lane;
        float s = 0.f;
        const float* qp = Qs[warp];
#pragma unroll 8
        for (int d = 0; d < 128; d++) s += qp[d] * Ks[lane][d];
        s *= scale;
        if (kcol > qrow) s = -INFINITY;

        float mt = s;
#pragma unroll
        for (int off = 16; off; off >>= 1) mt = fmaxf(mt, __shfl_xor_sync(0xffffffffu, mt, off));
        float mnew = fmaxf(mrun, mt);
        float corr = expf(mrun - mnew);
        float p = expf(s - mnew);
        float psum = p;
#pragma unroll
        for (int off = 16; off; off >>= 1) psum += __shfl_xor_sync(0xffffffffu, psum, off);
        lsum = lsum * corr + psum;
        o0 *= corr; o1 *= corr; o2 *= corr; o3 *= corr;

#pragma unroll
        for (int j = 0; j < 32; j++) {
            float pj = __shfl_sync(0xffffffffu, p, j);
            float4 v = *(const float4*)&Vs[j][lane * 4];
            o0 += pj * v.x; o1 += pj * v.y; o2 += pj * v.z; o3 += pj * v.w;
        }
        mrun = mnew;
    }

    float inv = 1.f / lsum;
    *(float4*)&ctx[((size_t)(b * SEQ + qrow)) * HID + h * HD + lane * 4] =
        make_float4(o0 * inv, o1 * inv, o2 * inv, o3 * inv);
}

// ---------------- launch ----------------
extern "C" void kernel_launch(void* const* d_in, const int* in_sizes, int n_in,
                              void* d_out, int out_size) {
    const float* hidden = (const float*)d_in[0];
    const int*   tt     = (const int*)d_in[1];
    const int*   pos    = (const int*)d_in[2];
    const float* wvq    = (const float*)d_in[3];
    const float* wlq    = (const float*)d_in[4];
    const float* wvd    = (const float*)d_in[5];
    const float* wld    = (const float*)d_in[6];
    float* out = (float*)d_out;

    float *qkv_p, *q_p, *k_p, *ctx_p;
    int* mask_p;
    cudaGetSymbolAddress((void**)&qkv_p, g_qkv);
    cudaGetSymbolAddress((void**)&q_p, g_q);
    cudaGetSymbolAddress((void**)&k_p, g_k);
    cudaGetSymbolAddress((void**)&ctx_p, g_ctx);
    cudaGetSymbolAddress((void**)&mask_p, g_mask);

    cudaFuncSetAttribute(gemm_tc, cudaFuncAttributeMaxDynamicSharedMemorySize, GEMM_SMEM);

    mask_kernel<<<MTOK / 256, 256>>>(tt, mask_p);

    // QKV projection: both experts, predicated store.
    // grid.x = M-blocks (fast-varying) so a wave shares B column tiles via L2.
    {
        dim3 grid(MTOK / BM, QKVN / BN);
        gemm_tc<<<grid, 256, GEMM_SMEM>>>(hidden, wvq, qkv_p, QKVN, mask_p, 1);
        gemm_tc<<<grid, 256, GEMM_SMEM>>>(hidden, wlq, qkv_p, QKVN, mask_p, 0);
    }

    // RoPE
    rope_kernel<<<(MTOK * NH * 64) / 256, 256>>>(qkv_p, pos, q_p, k_p);

    // Attention
    {
        dim3 grid(SEQ / 8, NH, BATCH);
        attn_kernel<<<grid, 256>>>(q_p, k_p, qkv_p, ctx_p);
    }

    // Dense projection: both experts, predicated store into d_out
    {
        dim3 grid(MTOK / BM, HID / BN);
        gemm_tc<<<grid, 256, GEMM_SMEM>>>(ctx_p, wvd, out, HID, mask_p, 1);
        gemm_tc<<<grid, 256, GEMM_SMEM>>>(ctx_p, wld, out, HID, mask_p, 0);
    }
}

// round 4
// speedup vs baseline: 3.0402x; 1.2848x over previous
#include <cuda_runtime.h>
#include <cuda_bf16.h>
#include <math.h>
#include <stdint.h>

// Problem constants
#define BATCH 2
#define SEQ   2048
#define NH    32
#define HD    128
#define HID   4096           // NH*HD
#define QKVN  12288          // 3*HID
#define MTOK  (BATCH*SEQ)    // 4096 tokens

// GEMM tile config (mma.sync m16n8k8 tf32)
#define BM 128
#define BN 128
#define BK 32
#define STAGES 3
#define AS_STRIDE 36
#define BS_STRIDE 136
#define AS_BYTES (BM * AS_STRIDE * 4)
#define BS_BYTES (BK * BS_STRIDE * 4)
#define STAGE_BYTES (AS_BYTES + BS_BYTES)
#define GEMM_SMEM (STAGES * STAGE_BYTES)            // 107520

// ---------------- scratch (device globals) -------------
__device__ float g_qkv[(size_t)MTOK * QKVN];
__device__ float g_q[(size_t)MTOK * HID];
__device__ float g_k[(size_t)MTOK * HID];
__device__ float g_ctx[(size_t)MTOK * HID];
__device__ int   g_cnt[2];            // [0]=vision count, [1]=language count
__device__ int   g_idx[2][MTOK];      // row index lists per expert

// ---------------- helpers ----------------
__device__ __forceinline__ uint32_t smem_u32(const void* p) {
    uint32_t a;
    asm("{ .reg .u64 t; cvta.to.shared.u64 t, %1; cvt.u32.u64 %0, t; }" : "=r"(a) : "l"(p));
    return a;
}
__device__ __forceinline__ void cp16(uint32_t dst, const void* src) {
    asm volatile("cp.async.cg.shared.global [%0], [%1], 16;" :: "r"(dst), "l"(src));
}
__device__ __forceinline__ void cp_commit() {
    asm volatile("cp.async.commit_group;" ::: "memory");
}
template <int N>
__device__ __forceinline__ void cp_wait() {
    asm volatile("cp.async.wait_group %0;" :: "n"(N) : "memory");
}
__device__ __forceinline__ uint32_t f2tf32(float f) {
    uint32_t r;
    asm("cvt.rna.tf32.f32 %0, %1;" : "=r"(r) : "f"(f));
    return r;
}
__device__ __forceinline__ void mma_tf32(float* c, uint32_t a0, uint32_t a1, uint32_t a2, uint32_t a3,
                                         uint32_t b0, uint32_t b1) {
    asm volatile(
        "mma.sync.aligned.m16n8k8.row.col.f32.tf32.tf32.f32 "
        "{%0,%1,%2,%3}, {%4,%5,%6,%7}, {%8,%9}, {%0,%1,%2,%3};"
        : "+f"(c[0]), "+f"(c[1]), "+f"(c[2]), "+f"(c[3])
        : "r"(a0), "r"(a1), "r"(a2), "r"(a3), "r"(b0), "r"(b1));
}

// ---------------- mask / routing ----------------
__global__ void zero_cnt_kernel() {
    if (threadIdx.x < 2) g_cnt[threadIdx.x] = 0;
}
__global__ void route_kernel(const int* __restrict__ tt) {
    int idx = blockIdx.x * blockDim.x + threadIdx.x;
    if (idx >= MTOK) return;
    int s = idx & (SEQ - 1);
    int vis = (s + 1 < SEQ) && (tt[idx] == 1) && (tt[idx + 1] == 1);
    int e = vis ? 0 : 1;
    int pos = atomicAdd(&g_cnt[e], 1);
    g_idx[e][pos] = idx;
}

// ---------------- tensor-core tf32 GEMM over gathered expert rows ----------------
// packed row r -> global row idx[r]; only rows r < *cnt_ptr are real/stored.
__global__ __launch_bounds__(256)
void gemm_tc(const float* __restrict__ A, const float* __restrict__ W,
             float* __restrict__ C, int N,
             const int* __restrict__ idx, const int* __restrict__ cnt_ptr) {
    __shared__ int idx_s[BM];
    extern __shared__ char smem[];
    const uint32_t sb = smem_u32(smem);
    const int tid = threadIdx.x;
    const int wid = tid >> 5;
    const int lane = tid & 31;
    const int lm = lane >> 2;
    const int lq = lane & 3;
    const int warp_m = wid & 1;
    const int warp_n = wid >> 1;
    const int m0 = blockIdx.x * BM;
    const int n0 = blockIdx.y * BN;

    const int count = __ldg(cnt_ptr);
    if (m0 >= count) return;

    if (tid < BM) {
        int mp = m0 + tid;
        idx_s[tid] = idx[mp < count ? mp : count - 1];
    }
    __syncthreads();

    const float* Wg = W + n0;

    int a_r[4], a_c[4], b_r[4], b_c[4];
#pragma unroll
    for (int i = 0; i < 4; i++) {
        int t = tid + i * 256;
        a_r[i] = t >> 3; a_c[i] = t & 7;
        b_r[i] = t >> 5; b_c[i] = t & 31;
    }
    int a_g[4];
#pragma unroll
    for (int i = 0; i < 4; i++) a_g[i] = idx_s[a_r[i]];

    auto load_stage = [&](int stage, int chunk) {
        uint32_t as = sb + stage * STAGE_BYTES;
        uint32_t bs = as + AS_BYTES;
        const float* Bsrc = Wg + (size_t)chunk * BK * N;
#pragma unroll
        for (int i = 0; i < 4; i++)
            cp16(as + a_r[i] * (AS_STRIDE * 4) + a_c[i] * 16,
                 A + (size_t)a_g[i] * HID + chunk * BK + a_c[i] * 4);
#pragma unroll
        for (int i = 0; i < 4; i++)
            cp16(bs + b_r[i] * (BS_STRIDE * 4) + b_c[i] * 16,
                 Bsrc + (size_t)b_r[i] * N + b_c[i] * 4);
    };

    float c[4][4][4];
#pragma unroll
    for (int mt = 0; mt < 4; mt++)
#pragma unroll
        for (int nt = 0; nt < 4; nt++)
#pragma unroll
            for (int j = 0; j < 4; j++) c[mt][nt][j] = 0.f;

    const int NC = HID / BK;

    load_stage(0, 0); cp_commit();
    load_stage(1, 1); cp_commit();

    for (int ch = 0; ch < NC; ch++) {
        cp_wait<1>();
        __syncthreads();

        if (ch + 2 < NC) load_stage((ch + 2) % STAGES, ch + 2);
        cp_commit();

        const float* As = (const float*)(smem + (ch % STAGES) * STAGE_BYTES);
        const float* Bs = (const float*)(smem + (ch % STAGES) * STAGE_BYTES + AS_BYTES);

#pragma unroll
        for (int kk = 0; kk < BK; kk += 8) {
            uint32_t af[4][4], bf[4][2];
#pragma unroll
            for (int mt = 0; mt < 4; mt++) {
                int r = warp_m * 64 + mt * 16 + lm;
                const float* ap = As + r * AS_STRIDE + kk + lq;
                af[mt][0] = f2tf32(ap[0]);
                af[mt][1] = f2tf32(ap[8 * AS_STRIDE]);
                af[mt][2] = f2tf32(ap[4]);
                af[mt][3] = f2tf32(ap[8 * AS_STRIDE + 4]);
            }
#pragma unroll
            for (int nt = 0; nt < 4; nt++) {
                int col = warp_n * 32 + nt * 8 + lm;
                const float* bp = Bs + (kk + lq) * BS_STRIDE + col;
                bf[nt][0] = f2tf32(bp[0]);
                bf[nt][1] = f2tf32(bp[4 * BS_STRIDE]);
            }
#pragma unroll
            for (int mt = 0; mt < 4; mt++)
#pragma unroll
                for (int nt = 0; nt < 4; nt++)
                    mma_tf32(c[mt][nt], af[mt][0], af[mt][1], af[mt][2], af[mt][3],
                             bf[nt][0], bf[nt][1]);
        }
        __syncthreads();
    }

    // epilogue: scatter to true rows; skip padding rows
#pragma unroll
    for (int mt = 0; mt < 4; mt++) {
        int r0 = warp_m * 64 + mt * 16 + lm;
        int r1 = r0 + 8;
        bool on0 = (m0 + r0 < count);
        bool on1 = (m0 + r1 < count);
        float* p0 = C + (size_t)idx_s[r0] * N + n0 + warp_n * 32;
        float* p1 = C + (size_t)idx_s[r1] * N + n0 + warp_n * 32;
#pragma unroll
        for (int nt = 0; nt < 4; nt++) {
            int col = nt * 8 + 2 * lq;
            if (on0) *(float2*)(p0 + col) = make_float2(c[mt][nt][0], c[mt][nt][1]);
            if (on1) *(float2*)(p1 + col) = make_float2(c[mt][nt][2], c[mt][nt][3]);
        }
    }
}

// ---------------- RoPE ----------------
__global__ void rope_kernel(const float* __restrict__ qkv, const int* __restrict__ pos_ids,
                            float* __restrict__ q, float* __restrict__ k) {
    int idx = blockIdx.x * blockDim.x + threadIdx.x;
    if (idx >= MTOK * NH * 64) return;
    int i = idx & 63;
    int h = (idx >> 6) & 31;
    int m = idx >> 11;

    float pos = (float)pos_ids[m];
    float freq = expf(-(float)i * (9.210340371976184f / 64.f));
    float ang = pos * freq;
    float cv = cosf(ang);
    float sv = sinf(ang);

    const float* qs = qkv + (size_t)m * QKVN + h * HD;
    const float* ks = qs + HID;
    float q0 = qs[i], q1 = qs[i + 64];
    float k0 = ks[i], k1 = ks[i + 64];

    size_t o = (size_t)m * HID + h * HD;
    q[o + i]      = q0 * cv - q1 * sv;
    q[o + i + 64] = q1 * cv + q0 * sv;
    k[o + i]      = k0 * cv - k1 * sv;
    k[o + i + 64] = k1 * cv + k0 * sv;
}

// ---------------- causal flash attention (fp32, warp per query row) ----------------
__global__ __launch_bounds__(256)
void attn_kernel(const float* __restrict__ Q, const float* __restrict__ Kg,
                 const float* __restrict__ qkv, float* __restrict__ ctx) {
    const int b = blockIdx.z;
    const int h = blockIdx.y;
    const int warp = threadIdx.x >> 5;
    const int lane = threadIdx.x & 31;
    const int qrow = blockIdx.x * 8 + warp;

    __shared__ float Ks[32][129];
    __shared__ float Vs[32][128];
    __shared__ float Qs[8][128];

    {
        int f = threadIdx.x;
        int r = f >> 5;
        int c4 = (f & 31) << 2;
        *(float4*)&Qs[r][c4] =
            *(const float4*)&Q[((size_t)(b * SEQ + blockIdx.x * 8 + r)) * HID + h * HD + c4];
    }

    float o0 = 0.f, o1 = 0.f, o2 = 0.f, o3 = 0.f;
    float mrun = -INFINITY, lsum = 0.f;
    const float scale = 0.088388347648318447f;
    const int qmax = blockIdx.x * 8 + 7;
    const int ntiles = qmax / 32 + 1;

    for (int t = 0; t < ntiles; t++) {
        __syncthreads();
#pragma unroll
        for (int i = 0; i < 4; i++) {
            int f = threadIdx.x + i * 256;
            int r = f >> 5;
            int c4 = (f & 31) << 2;
            size_t row = (size_t)(b * SEQ + t * 32 + r);
            float4 kv = *(const float4*)&Kg[row * HID + h * HD + c4];
            Ks[r][c4 + 0] = kv.x; Ks[r][c4 + 1] = kv.y;
            Ks[r][c4 + 2] = kv.z; Ks[r][c4 + 3] = kv.w;
            *(float4*)&Vs[r][c4] =
                *(const float4*)&qkv[row * QKVN + 2 * HID + h * HD + c4];
        }
        __syncthreads();

        int kcol = t * 32 + lane;
        float s = 0.f;
        const float* qp = Qs[warp];
#pragma unroll 8
        for (int d = 0; d < 128; d++) s += qp[d] * Ks[lane][d];
        s *= scale;
        if (kcol > qrow) s = -INFINITY;

        float mt = s;
#pragma unroll
        for (int off = 16; off; off >>= 1) mt = fmaxf(mt, __shfl_xor_sync(0xffffffffu, mt, off));
        float mnew = fmaxf(mrun, mt);
        float corr = expf(mrun - mnew);
        float p = expf(s - mnew);
        float psum = p;
#pragma unroll
        for (int off = 16; off; off >>= 1) psum += __shfl_xor_sync(0xffffffffu, psum, off);
        lsum = lsum * corr + psum;
        o0 *= corr; o1 *= corr; o2 *= corr; o3 *= corr;

#pragma unroll
        for (int j = 0; j < 32; j++) {
            float pj = __shfl_sync(0xffffffffu, p, j);
            float4 v = *(const float4*)&Vs[j][lane * 4];
            o0 += pj * v.x; o1 += pj * v.y; o2 += pj * v.z; o3 += pj * v.w;
        }
        mrun = mnew;
    }

    float inv = 1.f / lsum;
    *(float4*)&ctx[((size_t)(b * SEQ + qrow)) * HID + h * HD + lane * 4] =
        make_float4(o0 * inv, o1 * inv, o2 * inv, o3 * inv);
}

// ---------------- launch ----------------
extern "C" void kernel_launch(void* const* d_in, const int* in_sizes, int n_in,
                              void* d_out, int out_size) {
    const float* hidden = (const float*)d_in[0];
    const int*   tt     = (const int*)d_in[1];
    const int*   pos    = (const int*)d_in[2];
    const float* wvq    = (const float*)d_in[3];
    const float* wlq    = (const float*)d_in[4];
    const float* wvd    = (const float*)d_in[5];
    const float* wld    = (const float*)d_in[6];
    float* out = (float*)d_out;

    float *qkv_p, *q_p, *k_p, *ctx_p;
    int *cnt_p, *idx_p;
    cudaGetSymbolAddress((void**)&qkv_p, g_qkv);
    cudaGetSymbolAddress((void**)&q_p, g_q);
    cudaGetSymbolAddress((void**)&k_p, g_k);
    cudaGetSymbolAddress((void**)&ctx_p, g_ctx);
    cudaGetSymbolAddress((void**)&cnt_p, g_cnt);
    cudaGetSymbolAddress((void**)&idx_p, g_idx);

    const int* cnt_vis  = cnt_p;
    const int* cnt_lang = cnt_p + 1;
    const int* idx_vis  = idx_p;
    const int* idx_lang = idx_p + MTOK;

    cudaFuncSetAttribute(gemm_tc, cudaFuncAttributeMaxDynamicSharedMemorySize, GEMM_SMEM);

    zero_cnt_kernel<<<1, 32>>>();
    route_kernel<<<MTOK / 256, 256>>>(tt);

    // QKV projection per expert over gathered rows (worst-case grid, early exit)
    {
        dim3 grid(MTOK / BM, QKVN / BN);
        gemm_tc<<<grid, 256, GEMM_SMEM>>>(hidden, wvq, qkv_p, QKVN, idx_vis, cnt_vis);
        gemm_tc<<<grid, 256, GEMM_SMEM>>>(hidden, wlq, qkv_p, QKVN, idx_lang, cnt_lang);
    }

    // RoPE
    rope_kernel<<<(MTOK * NH * 64) / 256, 256>>>(qkv_p, pos, q_p, k_p);

    // Attention
    {
        dim3 grid(SEQ / 8, NH, BATCH);
        attn_kernel<<<grid, 256>>>(q_p, k_p, qkv_p, ctx_p);
    }

    // Dense projection per expert
    {
        dim3 grid(MTOK / BM, HID / BN);
        gemm_tc<<<grid, 256, GEMM_SMEM>>>(ctx_p, wvd, out, HID, idx_vis, cnt_vis);
        gemm_tc<<<grid, 256, GEMM_SMEM>>>(ctx_p, wld, out, HID, idx_lang, cnt_lang);
    }
}

// round 5
// speedup vs baseline: 3.1912x; 1.0497x over previous
#include <cuda_runtime.h>
#include <cuda_bf16.h>
#include <math.h>
#include <stdint.h>

// Problem constants
#define BATCH 2
#define SEQ   2048
#define NH    32
#define HD    128
#define HID   4096           // NH*HD
#define QKVN  12288          // 3*HID
#define MTOK  (BATCH*SEQ)    // 4096 tokens

// GEMM tile config (mma.sync m16n8k8 tf32)
#define BM 128
#define BN 128
#define BK 32
#define STAGES 3
#define AS_STRIDE 36
#define BS_STRIDE 136
#define AS_BYTES (BM * AS_STRIDE * 4)
#define BS_BYTES (BK * BS_STRIDE * 4)
#define STAGE_BYTES (AS_BYTES + BS_BYTES)
#define GEMM_SMEM (STAGES * STAGE_BYTES)            // 107520

// ---------------- scratch (device globals) -------------
__device__ float g_qkv[(size_t)MTOK * QKVN];
__device__ float g_q[(size_t)MTOK * HID];
__device__ float g_k[(size_t)MTOK * HID];
__device__ float g_ctx[(size_t)MTOK * HID];          // rounded at attn store
__device__ float g_hidr[(size_t)MTOK * HID];         // tf32-rounded hidden
// tf32-rounded weights: [vq | lq | vd | ld]
#define WR_VQ 0
#define WR_LQ ((size_t)HID * QKVN)
#define WR_VD (2 * (size_t)HID * QKVN)
#define WR_LD (2 * (size_t)HID * QKVN + (size_t)HID * HID)
__device__ float g_wr[2 * (size_t)HID * QKVN + 2 * (size_t)HID * HID];
__device__ int   g_cnt[2];            // [0]=vision count, [1]=language count
__device__ int   g_idx[2][MTOK];      // row index lists per expert

// ---------------- helpers ----------------
__device__ __forceinline__ uint32_t smem_u32(const void* p) {
    uint32_t a;
    asm("{ .reg .u64 t; cvta.to.shared.u64 t, %1; cvt.u32.u64 %0, t; }" : "=r"(a) : "l"(p));
    return a;
}
__device__ __forceinline__ void cp16(uint32_t dst, const void* src) {
    asm volatile("cp.async.cg.shared.global [%0], [%1], 16;" :: "r"(dst), "l"(src));
}
__device__ __forceinline__ void cp_commit() {
    asm volatile("cp.async.commit_group;" ::: "memory");
}
template <int N>
__device__ __forceinline__ void cp_wait() {
    asm volatile("cp.async.wait_group %0;" :: "n"(N) : "memory");
}
__device__ __forceinline__ uint32_t f2tf32(float f) {
    uint32_t r;
    asm("cvt.rna.tf32.f32 %0, %1;" : "=r"(r) : "f"(f));
    return r;
}
__device__ __forceinline__ float tf32r(float f) { return __uint_as_float(f2tf32(f)); }
__device__ __forceinline__ void mma_tf32(float* c, uint32_t a0, uint32_t a1, uint32_t a2, uint32_t a3,
                                         uint32_t b0, uint32_t b1) {
    asm volatile(
        "mma.sync.aligned.m16n8k8.row.col.f32.tf32.tf32.f32 "
        "{%0,%1,%2,%3}, {%4,%5,%6,%7}, {%8,%9}, {%0,%1,%2,%3};"
        : "+f"(c[0]), "+f"(c[1]), "+f"(c[2]), "+f"(c[3])
        : "r"(a0), "r"(a1), "r"(a2), "r"(a3), "r"(b0), "r"(b1));
}

// ---------------- tf32 rounding pre-pass ----------------
__global__ __launch_bounds__(256)
void round_tf32_kernel(const float4* __restrict__ in, float4* __restrict__ out, int n4) {
    int i = blockIdx.x * blockDim.x + threadIdx.x;
    if (i >= n4) return;
    float4 v = in[i];
    out[i] = make_float4(tf32r(v.x), tf32r(v.y), tf32r(v.z), tf32r(v.w));
}

// ---------------- mask / routing ----------------
__global__ void zero_cnt_kernel() {
    if (threadIdx.x < 2) g_cnt[threadIdx.x] = 0;
}
__global__ void route_kernel(const int* __restrict__ tt) {
    int idx = blockIdx.x * blockDim.x + threadIdx.x;
    if (idx >= MTOK) return;
    int s = idx & (SEQ - 1);
    int vis = (s + 1 < SEQ) && (tt[idx] == 1) && (tt[idx + 1] == 1);
    int e = vis ? 0 : 1;
    int pos = atomicAdd(&g_cnt[e], 1);
    g_idx[e][pos] = idx;
}

// ---------------- tensor-core tf32 GEMM over gathered expert rows ----------------
// Inputs already tf32-rounded; inner loop feeds raw bits to mma.
__global__ __launch_bounds__(256)
void gemm_tc(const float* __restrict__ A, const float* __restrict__ W,
             float* __restrict__ C, int N,
             const int* __restrict__ idx, const int* __restrict__ cnt_ptr) {
    __shared__ int idx_s[BM];
    extern __shared__ char smem[];
    const uint32_t sb = smem_u32(smem);
    const int tid = threadIdx.x;
    const int wid = tid >> 5;
    const int lane = tid & 31;
    const int lm = lane >> 2;
    const int lq = lane & 3;
    const int warp_m = wid & 1;
    const int warp_n = wid >> 1;
    const int m0 = blockIdx.x * BM;
    const int n0 = blockIdx.y * BN;

    const int count = __ldg(cnt_ptr);
    if (m0 >= count) return;

    if (tid < BM) {
        int mp = m0 + tid;
        idx_s[tid] = idx[mp < count ? mp : count - 1];
    }
    __syncthreads();

    const float* Wg = W + n0;

    int a_r[4], a_c[4], b_r[4], b_c[4];
#pragma unroll
    for (int i = 0; i < 4; i++) {
        int t = tid + i * 256;
        a_r[i] = t >> 3; a_c[i] = t & 7;
        b_r[i] = t >> 5; b_c[i] = t & 31;
    }
    int a_g[4];
#pragma unroll
    for (int i = 0; i < 4; i++) a_g[i] = idx_s[a_r[i]];

    auto load_stage = [&](int stage, int chunk) {
        uint32_t as = sb + stage * STAGE_BYTES;
        uint32_t bs = as + AS_BYTES;
        const float* Bsrc = Wg + (size_t)chunk * BK * N;
#pragma unroll
        for (int i = 0; i < 4; i++)
            cp16(as + a_r[i] * (AS_STRIDE * 4) + a_c[i] * 16,
                 A + (size_t)a_g[i] * HID + chunk * BK + a_c[i] * 4);
#pragma unroll
        for (int i = 0; i < 4; i++)
            cp16(bs + b_r[i] * (BS_STRIDE * 4) + b_c[i] * 16,
                 Bsrc + (size_t)b_r[i] * N + b_c[i] * 4);
    };

    float c[4][4][4];
#pragma unroll
    for (int mt = 0; mt < 4; mt++)
#pragma unroll
        for (int nt = 0; nt < 4; nt++)
#pragma unroll
            for (int j = 0; j < 4; j++) c[mt][nt][j] = 0.f;

    const int NC = HID / BK;

    load_stage(0, 0); cp_commit();
    load_stage(1, 1); cp_commit();

    for (int ch = 0; ch < NC; ch++) {
        cp_wait<1>();
        __syncthreads();

        if (ch + 2 < NC) load_stage((ch + 2) % STAGES, ch + 2);
        cp_commit();

        const uint32_t* As = (const uint32_t*)(smem + (ch % STAGES) * STAGE_BYTES);
        const uint32_t* Bs = (const uint32_t*)(smem + (ch % STAGES) * STAGE_BYTES + AS_BYTES);

#pragma unroll
        for (int kk = 0; kk < BK; kk += 8) {
            uint32_t af[4][4], bf[4][2];
#pragma unroll
            for (int mt = 0; mt < 4; mt++) {
                int r = warp_m * 64 + mt * 16 + lm;
                const uint32_t* ap = As + r * AS_STRIDE + kk + lq;
                af[mt][0] = ap[0];
                af[mt][1] = ap[8 * AS_STRIDE];
                af[mt][2] = ap[4];
                af[mt][3] = ap[8 * AS_STRIDE + 4];
            }
#pragma unroll
            for (int nt = 0; nt < 4; nt++) {
                int col = warp_n * 32 + nt * 8 + lm;
                const uint32_t* bp = Bs + (kk + lq) * BS_STRIDE + col;
                bf[nt][0] = bp[0];
                bf[nt][1] = bp[4 * BS_STRIDE];
            }
#pragma unroll
            for (int mt = 0; mt < 4; mt++)
#pragma unroll
                for (int nt = 0; nt < 4; nt++)
                    mma_tf32(c[mt][nt], af[mt][0], af[mt][1], af[mt][2], af[mt][3],
                             bf[nt][0], bf[nt][1]);
        }
        __syncthreads();
    }

    // epilogue: scatter to true rows; skip padding rows
#pragma unroll
    for (int mt = 0; mt < 4; mt++) {
        int r0 = warp_m * 64 + mt * 16 + lm;
        int r1 = r0 + 8;
        bool on0 = (m0 + r0 < count);
        bool on1 = (m0 + r1 < count);
        float* p0 = C + (size_t)idx_s[r0] * N + n0 + warp_n * 32;
        float* p1 = C + (size_t)idx_s[r1] * N + n0 + warp_n * 32;
#pragma unroll
        for (int nt = 0; nt < 4; nt++) {
            int col = nt * 8 + 2 * lq;
            if (on0) *(float2*)(p0 + col) = make_float2(c[mt][nt][0], c[mt][nt][1]);
            if (on1) *(float2*)(p1 + col) = make_float2(c[mt][nt][2], c[mt][nt][3]);
        }
    }
}

// ---------------- RoPE ----------------
__global__ void rope_kernel(const float* __restrict__ qkv, const int* __restrict__ pos_ids,
                            float* __restrict__ q, float* __restrict__ k) {
    int idx = blockIdx.x * blockDim.x + threadIdx.x;
    if (idx >= MTOK * NH * 64) return;
    int i = idx & 63;
    int h = (idx >> 6) & 31;
    int m = idx >> 11;

    float pos = (float)pos_ids[m];
    float freq = expf(-(float)i * (9.210340371976184f / 64.f));
    float ang = pos * freq;
    float cv = cosf(ang);
    float sv = sinf(ang);

    const float* qs = qkv + (size_t)m * QKVN + h * HD;
    const float* ks = qs + HID;
    float q0 = qs[i], q1 = qs[i + 64];
    float k0 = ks[i], k1 = ks[i + 64];

    size_t o = (size_t)m * HID + h * HD;
    q[o + i]      = q0 * cv - q1 * sv;
    q[o + i + 64] = q1 * cv + q0 * sv;
    k[o + i]      = k0 * cv - k1 * sv;
    k[o + i + 64] = k1 * cv + k0 * sv;
}

// ---------------- causal flash attention (fp32, warp per query row) ----------------
__global__ __launch_bounds__(256)
void attn_kernel(const float* __restrict__ Q, const float* __restrict__ Kg,
                 const float* __restrict__ qkv, float* __restrict__ ctx) {
    const int b = blockIdx.z;
    const int h = blockIdx.y;
    const int warp = threadIdx.x >> 5;
    const int lane = threadIdx.x & 31;
    const int qrow = blockIdx.x * 8 + warp;

    __shared__ float Ks[32][129];
    __shared__ float Vs[32][128];
    __shared__ float Qs[8][128];

    {
        int f = threadIdx.x;
        int r = f >> 5;
        int c4 = (f & 31) << 2;
        *(float4*)&Qs[r][c4] =
            *(const float4*)&Q[((size_t)(b * SEQ + blockIdx.x * 8 + r)) * HID + h * HD + c4];
    }

    float o0 = 0.f, o1 = 0.f, o2 = 0.f, o3 = 0.f;
    float mrun = -INFINITY, lsum = 0.f;
    const float scale = 0.088388347648318447f;
    const int qmax = blockIdx.x * 8 + 7;
    const int ntiles = qmax / 32 + 1;

    for (int t = 0; t < ntiles; t++) {
        __syncthreads();
#pragma unroll
        for (int i = 0; i < 4; i++) {
            int f = threadIdx.x + i * 256;
            int r = f >> 5;
            int c4 = (f & 31) << 2;
            size_t row = (size_t)(b * SEQ + t * 32 + r);
            float4 kv = *(const float4*)&Kg[row * HID + h * HD + c4];
            Ks[r][c4 + 0] = kv.x; Ks[r][c4 + 1] = kv.y;
            Ks[r][c4 + 2] = kv.z; Ks[r][c4 + 3] = kv.w;
            *(float4*)&Vs[r][c4] =
                *(const float4*)&qkv[row * QKVN + 2 * HID + h * HD + c4];
        }
        __syncthreads();

        int kcol = t * 32 + lane;
        float s = 0.f;
        const float* qp = Qs[warp];
#pragma unroll 8
        for (int d = 0; d < 128; d++) s += qp[d] * Ks[lane][d];
        s *= scale;
        if (kcol > qrow) s = -INFINITY;

        float mt = s;
#pragma unroll
        for (int off = 16; off; off >>= 1) mt = fmaxf(mt, __shfl_xor_sync(0xffffffffu, mt, off));
        float mnew = fmaxf(mrun, mt);
        float corr = expf(mrun - mnew);
        float p = expf(s - mnew);
        float psum = p;
#pragma unroll
        for (int off = 16; off; off >>= 1) psum += __shfl_xor_sync(0xffffffffu, psum, off);
        lsum = lsum * corr + psum;
        o0 *= corr; o1 *= corr; o2 *= corr; o3 *= corr;

#pragma unroll
        for (int j = 0; j < 32; j++) {
            float pj = __shfl_sync(0xffffffffu, p, j);
            float4 v = *(const float4*)&Vs[j][lane * 4];
            o0 += pj * v.x; o1 += pj * v.y; o2 += pj * v.z; o3 += pj * v.w;
        }
        mrun = mnew;
    }

    // store tf32-rounded ctx: dense GEMM consumes it without in-loop cvt
    float inv = 1.f / lsum;
    *(float4*)&ctx[((size_t)(b * SEQ + qrow)) * HID + h * HD + lane * 4] =
        make_float4(tf32r(o0 * inv), tf32r(o1 * inv), tf32r(o2 * inv), tf32r(o3 * inv));
}

// ---------------- launch ----------------
extern "C" void kernel_launch(void* const* d_in, const int* in_sizes, int n_in,
                              void* d_out, int out_size) {
    const float* hidden = (const float*)d_in[0];
    const int*   tt     = (const int*)d_in[1];
    const int*   pos    = (const int*)d_in[2];
    const float* wvq    = (const float*)d_in[3];
    const float* wlq    = (const float*)d_in[4];
    const float* wvd    = (const float*)d_in[5];
    const float* wld    = (const float*)d_in[6];
    float* out = (float*)d_out;

    float *qkv_p, *q_p, *k_p, *ctx_p, *hidr_p, *wr_p;
    int *cnt_p, *idx_p;
    cudaGetSymbolAddress((void**)&qkv_p, g_qkv);
    cudaGetSymbolAddress((void**)&q_p, g_q);
    cudaGetSymbolAddress((void**)&k_p, g_k);
    cudaGetSymbolAddress((void**)&ctx_p, g_ctx);
    cudaGetSymbolAddress((void**)&hidr_p, g_hidr);
    cudaGetSymbolAddress((void**)&wr_p, g_wr);
    cudaGetSymbolAddress((void**)&cnt_p, g_cnt);
    cudaGetSymbolAddress((void**)&idx_p, g_idx);

    const int* cnt_vis  = cnt_p;
    const int* cnt_lang = cnt_p + 1;
    const int* idx_vis  = idx_p;
    const int* idx_lang = idx_p + MTOK;

    float* wr_vq = wr_p + WR_VQ;
    float* wr_lq = wr_p + WR_LQ;
    float* wr_vd = wr_p + WR_VD;
    float* wr_ld = wr_p + WR_LD;

    cudaFuncSetAttribute(gemm_tc, cudaFuncAttributeMaxDynamicSharedMemorySize, GEMM_SMEM);

    zero_cnt_kernel<<<1, 32>>>();
    route_kernel<<<MTOK / 256, 256>>>(tt);

    // tf32 rounding pre-pass
    {
        int n4w = (int)((size_t)HID * QKVN / 4);
        round_tf32_kernel<<<(n4w + 255) / 256, 256>>>((const float4*)wvq, (float4*)wr_vq, n4w);
        round_tf32_kernel<<<(n4w + 255) / 256, 256>>>((const float4*)wlq, (float4*)wr_lq, n4w);
        int n4d = (int)((size_t)HID * HID / 4);
        round_tf32_kernel<<<(n4d + 255) / 256, 256>>>((const float4*)wvd, (float4*)wr_vd, n4d);
        round_tf32_kernel<<<(n4d + 255) / 256, 256>>>((const float4*)wld, (float4*)wr_ld, n4d);
        int n4h = (int)((size_t)MTOK * HID / 4);
        round_tf32_kernel<<<(n4h + 255) / 256, 256>>>((const float4*)hidden, (float4*)hidr_p, n4h);
    }

    // QKV projection per expert over gathered rows
    {
        dim3 grid(MTOK / BM, QKVN / BN);
        gemm_tc<<<grid, 256, GEMM_SMEM>>>(hidr_p, wr_vq, qkv_p, QKVN, idx_vis, cnt_vis);
        gemm_tc<<<grid, 256, GEMM_SMEM>>>(hidr_p, wr_lq, qkv_p, QKVN, idx_lang, cnt_lang);
    }

    // RoPE
    rope_kernel<<<(MTOK * NH * 64) / 256, 256>>>(qkv_p, pos, q_p, k_p);

    // Attention
    {
        dim3 grid(SEQ / 8, NH, BATCH);
        attn_kernel<<<grid, 256>>>(q_p, k_p, qkv_p, ctx_p);
    }

    // Dense projection per expert
    {
        dim3 grid(MTOK / BM, HID / BN);
        gemm_tc<<<grid, 256, GEMM_SMEM>>>(ctx_p, wr_vd, out, HID, idx_vis, cnt_vis);
        gemm_tc<<<grid, 256, GEMM_SMEM>>>(ctx_p, wr_ld, out, HID, idx_lang, cnt_lang);
    }
}